// round 1
// baseline (speedup 1.0000x reference)
#include <cuda_runtime.h>
#include <math.h>

// Problem constants
#define Bz 4
#define Sz 2048
#define Dz 1024
#define Hz 16
#define HDz 64
#define D3z 3072

// Scratch (device globals: allocation-free per harness rules)
__device__ float g_qkv[(size_t)Bz * Sz * D3z];   // [8192, 3072]
__device__ float g_attn[(size_t)Bz * Sz * Dz];   // [8192, 1024]

// ---------------------------------------------------------------------------
// NT GEMM: C[M,N] = A[M,K] * B[N,K]^T  (both row-major, K contiguous)
// 128x128 block tile, BK=8, 256 threads, 8x8 register micro-tile.
// ---------------------------------------------------------------------------
__global__ __launch_bounds__(256, 2) void gemm_nt_kernel(
    const float* __restrict__ A, const float* __restrict__ B,
    float* __restrict__ C, int M, int N, int K)
{
    __shared__ float As[8][132];   // stride 132: float4-aligned, conflict-free
    __shared__ float Bs[8][132];

    const int tid  = threadIdx.x;
    const int m0   = blockIdx.y * 128;
    const int n0   = blockIdx.x * 128;
    const int tx   = tid & 15;
    const int ty   = tid >> 4;
    const int lrow = tid >> 1;        // 0..127
    const int lk   = (tid & 1) * 4;   // 0 or 4

    const float* Ap = A + (size_t)(m0 + lrow) * K + lk;
    const float* Bp = B + (size_t)(n0 + lrow) * K + lk;

    float acc[8][8];
    #pragma unroll
    for (int i = 0; i < 8; i++)
        #pragma unroll
        for (int j = 0; j < 8; j++) acc[i][j] = 0.f;

    for (int k0 = 0; k0 < K; k0 += 8) {
        float4 av = *(const float4*)(Ap + k0);
        float4 bv = *(const float4*)(Bp + k0);
        __syncthreads();
        As[lk + 0][lrow] = av.x; As[lk + 1][lrow] = av.y;
        As[lk + 2][lrow] = av.z; As[lk + 3][lrow] = av.w;
        Bs[lk + 0][lrow] = bv.x; Bs[lk + 1][lrow] = bv.y;
        Bs[lk + 2][lrow] = bv.z; Bs[lk + 3][lrow] = bv.w;
        __syncthreads();
        #pragma unroll
        for (int k = 0; k < 8; k++) {
            float4 a0 = *(const float4*)&As[k][ty * 8];
            float4 a1 = *(const float4*)&As[k][ty * 8 + 4];
            float4 b0 = *(const float4*)&Bs[k][tx * 8];
            float4 b1 = *(const float4*)&Bs[k][tx * 8 + 4];
            float a[8] = {a0.x, a0.y, a0.z, a0.w, a1.x, a1.y, a1.z, a1.w};
            float b[8] = {b0.x, b0.y, b0.z, b0.w, b1.x, b1.y, b1.z, b1.w};
            #pragma unroll
            for (int mm = 0; mm < 8; mm++)
                #pragma unroll
                for (int nn = 0; nn < 8; nn++)
                    acc[mm][nn] = fmaf(a[mm], b[nn], acc[mm][nn]);
        }
    }

    #pragma unroll
    for (int mm = 0; mm < 8; mm++) {
        float* cp = C + (size_t)(m0 + ty * 8 + mm) * N + n0 + tx * 8;
        float4 v0 = make_float4(acc[mm][0], acc[mm][1], acc[mm][2], acc[mm][3]);
        float4 v1 = make_float4(acc[mm][4], acc[mm][5], acc[mm][6], acc[mm][7]);
        *(float4*)cp       = v0;
        *(float4*)(cp + 4) = v1;
    }
}

// ---------------------------------------------------------------------------
// Flash attention, fp32. One block per (q-tile=64, head, batch).
// 256 threads: thread = (row i = tid/4, d-group g = tid%4, 16 dims each).
// Q tile scaled by 1/sqrt(64) at load, then held in registers.
// P tile staged through SMEM (aliased onto the Q tile region).
// ---------------------------------------------------------------------------
#define TS 68                       // tile row stride (floats): float4-aligned, conflict-free
#define ATT_SMEM (3 * 64 * TS * 4)  // Qs(/Ps) + Ks + Vs = 52224 bytes

__global__ __launch_bounds__(256, 2) void attn_kernel(
    const float* __restrict__ qkv, float* __restrict__ out)
{
    extern __shared__ float sm[];
    float* Qs = sm;                 // aliased as Ps after q is in registers
    float* Ks = sm + 64 * TS;
    float* Vs = sm + 2 * 64 * TS;
    float* Ps = Qs;

    const int tid = threadIdx.x;
    const int qt  = blockIdx.x;     // 0..31
    const int h   = blockIdx.y;     // 0..15
    const int b   = blockIdx.z;     // 0..3
    const int q0  = qt * 64;
    const size_t bhbase = (size_t)b * Sz * D3z + (size_t)h * HDz;

    // Load Q tile (scaled)
    for (int idx = tid; idx < 1024; idx += 256) {
        int r  = idx >> 4;
        int d4 = (idx & 15) << 2;
        float4 v = *(const float4*)(qkv + bhbase + (size_t)(q0 + r) * D3z + d4);
        float* q = Qs + r * TS + d4;
        q[0] = v.x * 0.125f; q[1] = v.y * 0.125f;
        q[2] = v.z * 0.125f; q[3] = v.w * 0.125f;
    }
    __syncthreads();

    const int i = tid >> 2;   // query row within tile
    const int g = tid & 3;    // d-group / j-group

    float4 qv[16];
    #pragma unroll
    for (int dw = 0; dw < 16; dw++)
        qv[dw] = *(const float4*)&Qs[i * TS + 4 * dw];

    float4 o0 = make_float4(0, 0, 0, 0), o1 = o0, o2 = o0, o3 = o0;
    float m = -__int_as_float(0x7f800000);  // -inf
    float l = 0.f;

    for (int kt = 0; kt <= qt; kt++) {
        const int k0 = kt * 64;
        __syncthreads();   // protect Ks/Vs/Ps from previous iteration's readers
        for (int idx = tid; idx < 1024; idx += 256) {
            int r  = idx >> 4;
            int d4 = (idx & 15) << 2;
            const float* kp = qkv + bhbase + (size_t)(k0 + r) * D3z + Dz + d4;
            float4 kvv = *(const float4*)kp;
            float4 vvv = *(const float4*)(kp + Dz);
            *(float4*)&Ks[r * TS + d4] = kvv;
            *(float4*)&Vs[r * TS + d4] = vvv;
        }
        __syncthreads();

        // Scores: thread handles j = g + 4*jj, jj = 0..15
        float s[16];
        #pragma unroll
        for (int jj = 0; jj < 16; jj++) {
            const float4* kr = (const float4*)&Ks[(g + 4 * jj) * TS];
            float acc = 0.f;
            #pragma unroll
            for (int dw = 0; dw < 16; dw++) {
                float4 k4 = kr[dw];
                acc = fmaf(qv[dw].x, k4.x, acc);
                acc = fmaf(qv[dw].y, k4.y, acc);
                acc = fmaf(qv[dw].z, k4.z, acc);
                acc = fmaf(qv[dw].w, k4.w, acc);
            }
            s[jj] = acc;
        }

        if (kt == qt) {   // causal mask within diagonal tile
            #pragma unroll
            for (int jj = 0; jj < 16; jj++)
                if (g + 4 * jj > i) s[jj] = -__int_as_float(0x7f800000);
        }

        // Online softmax (reduce across the 4 lanes sharing row i)
        float tmax = s[0];
        #pragma unroll
        for (int jj = 1; jj < 16; jj++) tmax = fmaxf(tmax, s[jj]);
        tmax = fmaxf(tmax, __shfl_xor_sync(0xffffffffu, tmax, 1));
        tmax = fmaxf(tmax, __shfl_xor_sync(0xffffffffu, tmax, 2));

        float newm  = fmaxf(m, tmax);
        float alpha = __expf(m - newm);   // m=-inf on first tile -> alpha=0
        float rsum = 0.f;
        #pragma unroll
        for (int jj = 0; jj < 16; jj++) {
            float p = __expf(s[jj] - newm);
            s[jj] = p;
            rsum += p;
        }
        rsum += __shfl_xor_sync(0xffffffffu, rsum, 1);
        rsum += __shfl_xor_sync(0xffffffffu, rsum, 2);
        m = newm;
        l = l * alpha + rsum;

        o0.x *= alpha; o0.y *= alpha; o0.z *= alpha; o0.w *= alpha;
        o1.x *= alpha; o1.y *= alpha; o1.z *= alpha; o1.w *= alpha;
        o2.x *= alpha; o2.y *= alpha; o2.z *= alpha; o2.w *= alpha;
        o3.x *= alpha; o3.y *= alpha; o3.z *= alpha; o3.w *= alpha;

        #pragma unroll
        for (int jj = 0; jj < 16; jj++)
            Ps[i * TS + g + 4 * jj] = s[jj];
        __syncthreads();

        // O += P * V   (thread accumulates dims [g*16, g*16+16) over all 64 j)
        #pragma unroll 8
        for (int j = 0; j < 64; j++) {
            float p = Ps[i * TS + j];
            const float4* vr = (const float4*)&Vs[j * TS + g * 16];
            float4 v0 = vr[0], v1 = vr[1], v2 = vr[2], v3 = vr[3];
            o0.x = fmaf(p, v0.x, o0.x); o0.y = fmaf(p, v0.y, o0.y);
            o0.z = fmaf(p, v0.z, o0.z); o0.w = fmaf(p, v0.w, o0.w);
            o1.x = fmaf(p, v1.x, o1.x); o1.y = fmaf(p, v1.y, o1.y);
            o1.z = fmaf(p, v1.z, o1.z); o1.w = fmaf(p, v1.w, o1.w);
            o2.x = fmaf(p, v2.x, o2.x); o2.y = fmaf(p, v2.y, o2.y);
            o2.z = fmaf(p, v2.z, o2.z); o2.w = fmaf(p, v2.w, o2.w);
            o3.x = fmaf(p, v3.x, o3.x); o3.y = fmaf(p, v3.y, o3.y);
            o3.z = fmaf(p, v3.z, o3.z); o3.w = fmaf(p, v3.w, o3.w);
        }
    }

    float inv = 1.f / l;
    o0.x *= inv; o0.y *= inv; o0.z *= inv; o0.w *= inv;
    o1.x *= inv; o1.y *= inv; o1.z *= inv; o1.w *= inv;
    o2.x *= inv; o2.y *= inv; o2.z *= inv; o2.w *= inv;
    o3.x *= inv; o3.y *= inv; o3.z *= inv; o3.w *= inv;

    float* op = out + (size_t)(b * Sz + q0 + i) * Dz + h * HDz + g * 16;
    *(float4*)op        = o0;
    *(float4*)(op + 4)  = o1;
    *(float4*)(op + 8)  = o2;
    *(float4*)(op + 12) = o3;
}

// ---------------------------------------------------------------------------
extern "C" void kernel_launch(void* const* d_in, const int* in_sizes, int n_in,
                              void* d_out, int out_size)
{
    const float* x      = (const float*)d_in[0];
    const float* w_qkv  = (const float*)d_in[1];
    const float* w_proj = (const float*)d_in[2];
    float* out = (float*)d_out;

    void* qkvp = nullptr;
    void* attnp = nullptr;
    cudaGetSymbolAddress(&qkvp, g_qkv);
    cudaGetSymbolAddress(&attnp, g_attn);
    cudaFuncSetAttribute(attn_kernel,
                         cudaFuncAttributeMaxDynamicSharedMemorySize, ATT_SMEM);

    const int M = Bz * Sz;  // 8192

    // 1) QKV projection: [8192,1024] x [3072,1024]^T -> [8192,3072]
    gemm_nt_kernel<<<dim3(D3z / 128, M / 128), 256>>>(
        x, w_qkv, (float*)qkvp, M, D3z, Dz);

    // 2) Causal flash attention -> g_attn [8192,1024]
    attn_kernel<<<dim3(Sz / 64, Hz, Bz), 256, ATT_SMEM>>>(
        (const float*)qkvp, (float*)attnp);

    // 3) Output projection: [8192,1024] x [1024,1024]^T -> d_out
    gemm_nt_kernel<<<dim3(Dz / 128, M / 128), 256>>>(
        (const float*)attnp, w_proj, out, M, Dz, Dz);
}

// round 3
// speedup vs baseline: 1.2818x; 1.2818x over previous
#include <cuda_runtime.h>
#include <cstdint>
#include <math.h>

// Problem constants
#define Bz 4
#define Sz 2048
#define Dz 1024
#define Hz 16
#define HDz 64
#define D3z 3072
#define Mz (Bz * Sz)

// Scratch (device globals: allocation-free per harness rules)
__device__ float g_qkv[(size_t)Mz * D3z];   // [8192, 3072]
__device__ float g_attn[(size_t)Mz * Dz];   // [8192, 1024]
__device__ float g_x[(size_t)Mz * Dz];      // tf32-rounded x
__device__ float g_wq[(size_t)D3z * Dz];    // tf32-rounded w_qkv
__device__ float g_wp[(size_t)Dz * Dz];     // tf32-rounded w_proj

// ---------------------------------------------------------------------------
// Helpers
// ---------------------------------------------------------------------------
__device__ __forceinline__ uint32_t smem_u32(const void* p) {
    uint32_t a;
    asm("{ .reg .u64 t; cvta.to.shared.u64 t, %1; cvt.u32.u64 %0, t; }"
        : "=r"(a) : "l"(p));
    return a;
}

#define CP_ASYNC16(dst, src) \
    asm volatile("cp.async.cg.shared.global [%0], [%1], 16;" \
        :: "r"((uint32_t)(dst)), "l"(src) : "memory")
#define CP_COMMIT() asm volatile("cp.async.commit_group;" ::: "memory")
#define CP_WAIT2() asm volatile("cp.async.wait_group 2;" ::: "memory")
#define CP_WAIT1() asm volatile("cp.async.wait_group 1;" ::: "memory")
#define CP_WAIT0() asm volatile("cp.async.wait_group 0;" ::: "memory")

// m16n8k8 tf32 MMA (sm_80+, valid at compute_103)
__device__ __forceinline__ void mma_tf32(
    float& d0, float& d1, float& d2, float& d3,
    uint32_t a0, uint32_t a1, uint32_t a2, uint32_t a3,
    uint32_t b0, uint32_t b1)
{
    asm volatile(
        "mma.sync.aligned.m16n8k8.row.col.f32.tf32.tf32.f32 "
        "{%0,%1,%2,%3}, {%4,%5,%6,%7}, {%8,%9}, {%0,%1,%2,%3};"
        : "+f"(d0), "+f"(d1), "+f"(d2), "+f"(d3)
        : "r"(a0), "r"(a1), "r"(a2), "r"(a3), "r"(b0), "r"(b1));
}

// ---------------------------------------------------------------------------
// tf32 round-to-nearest conversion (in 32-bit containers)
// ---------------------------------------------------------------------------
__global__ __launch_bounds__(256) void cvt_tf32_kernel(
    const float* __restrict__ in, float* __restrict__ out, int n4)
{
    int i = blockIdx.x * blockDim.x + threadIdx.x;
    if (i >= n4) return;
    float4 v = ((const float4*)in)[i];
    uint4 o;
    asm("cvt.rna.tf32.f32 %0, %1;" : "=r"(o.x) : "f"(v.x));
    asm("cvt.rna.tf32.f32 %0, %1;" : "=r"(o.y) : "f"(v.y));
    asm("cvt.rna.tf32.f32 %0, %1;" : "=r"(o.z) : "f"(v.z));
    asm("cvt.rna.tf32.f32 %0, %1;" : "=r"(o.w) : "f"(v.w));
    ((uint4*)out)[i] = o;
}

// ---------------------------------------------------------------------------
// tf32 mma.sync NT GEMM: C[M,N] = A[M,K] * B[N,K]^T (row-major, K contiguous).
// 128x128 CTA, BK=32, 256 threads (8 warps: 4M x 2N, warp tile 32x64).
// cp.async 4-stage pipeline. SMEM stride 36 floats -> conflict-free frag LDS.
// ---------------------------------------------------------------------------
#define STAGES 4
#define BK 32
#define AST 36                          // padded floats per SMEM row
#define STAGE_FLOATS (128 * AST * 2)    // A tile + B tile
#define GEMM_SMEM (STAGES * STAGE_FLOATS * 4)   // 147456 bytes

__global__ __launch_bounds__(256, 1)
void gemm_mma_kernel(const float* __restrict__ A, const float* __restrict__ B,
                     float* __restrict__ C, int M, int N, int K)
{
    extern __shared__ float smf[];
    uint32_t sb = smem_u32(smf);
    const int tid = threadIdx.x;
    const int wid = tid >> 5;
    const int l   = tid & 31;
    const int g   = l >> 2;     // group-of-4 id (row within frag)
    const int tg  = l & 3;      // thread-in-group (col within frag)
    const int wm  = wid >> 1;   // 0..3 -> M offset wm*32
    const int wn  = wid & 1;    // 0..1 -> N offset wn*64
    const int m0  = blockIdx.y * 128;
    const int n0  = blockIdx.x * 128;
    const int nchunk = K / BK;

    auto issue = [&](int c, int s) {
        uint32_t sA = sb + (uint32_t)s * STAGE_FLOATS * 4;
        uint32_t sB = sA + 128u * AST * 4;
        const float* Ab = A + (size_t)m0 * K + c * BK;
        const float* Bb = B + (size_t)n0 * K + c * BK;
        #pragma unroll
        for (int i = 0; i < 4; i++) {
            int idx = tid + 256 * i;      // 0..1023
            int row = idx >> 3;
            int c4  = idx & 7;
            uint32_t so = (uint32_t)(row * AST + c4 * 4) * 4;
            CP_ASYNC16(sA + so, Ab + (size_t)row * K + c4 * 4);
            CP_ASYNC16(sB + so, Bb + (size_t)row * K + c4 * 4);
        }
        CP_COMMIT();
    };

    float acc[2][8][4];
    #pragma unroll
    for (int mt = 0; mt < 2; mt++)
        #pragma unroll
        for (int nt = 0; nt < 8; nt++)
            #pragma unroll
            for (int q = 0; q < 4; q++) acc[mt][nt][q] = 0.f;

    #pragma unroll
    for (int s = 0; s < STAGES - 1; s++) issue(s, s);

    for (int c = 0; c < nchunk; c++) {
        int pa = nchunk - 1 - c;
        if (pa >= 2)      { CP_WAIT2(); }
        else if (pa == 1) { CP_WAIT1(); }
        else              { CP_WAIT0(); }
        __syncthreads();

        int cn = c + STAGES - 1;
        if (cn < nchunk) issue(cn, cn & (STAGES - 1));

        const float* As = smf + (size_t)(c & (STAGES - 1)) * STAGE_FLOATS;
        const float* Bs = As + 128 * AST;
        const uint32_t* Au = (const uint32_t*)As;
        const uint32_t* Bu = (const uint32_t*)Bs;

        #pragma unroll
        for (int s4 = 0; s4 < 4; s4++) {   // k-steps of 8
            uint32_t a[2][4];
            #pragma unroll
            for (int mt = 0; mt < 2; mt++) {
                int base = (wm * 32 + mt * 16 + g) * AST + s4 * 8 + tg;
                a[mt][0] = Au[base];
                a[mt][1] = Au[base + 8 * AST];
                a[mt][2] = Au[base + 4];
                a[mt][3] = Au[base + 8 * AST + 4];
            }
            uint32_t b[8][2];
            #pragma unroll
            for (int nt = 0; nt < 8; nt++) {
                int base = (wn * 64 + nt * 8 + g) * AST + s4 * 8 + tg;
                b[nt][0] = Bu[base];
                b[nt][1] = Bu[base + 4];
            }
            #pragma unroll
            for (int mt = 0; mt < 2; mt++)
                #pragma unroll
                for (int nt = 0; nt < 8; nt++)
                    mma_tf32(acc[mt][nt][0], acc[mt][nt][1],
                             acc[mt][nt][2], acc[mt][nt][3],
                             a[mt][0], a[mt][1], a[mt][2], a[mt][3],
                             b[nt][0], b[nt][1]);
        }
    }

    // Epilogue: direct float2 stores to C
    #pragma unroll
    for (int mt = 0; mt < 2; mt++) {
        int r = m0 + wm * 32 + mt * 16 + g;
        #pragma unroll
        for (int nt = 0; nt < 8; nt++) {
            int cc = n0 + wn * 64 + nt * 8 + tg * 2;
            *(float2*)&C[(size_t)r * N + cc] =
                make_float2(acc[mt][nt][0], acc[mt][nt][1]);
            *(float2*)&C[(size_t)(r + 8) * N + cc] =
                make_float2(acc[mt][nt][2], acc[mt][nt][3]);
        }
    }
}

// ---------------------------------------------------------------------------
// Flash attention, fp32 (unchanged from R1 — passed at rel_err 9.5e-7)
// ---------------------------------------------------------------------------
#define TS 68
#define ATT_SMEM (3 * 64 * TS * 4)

__global__ __launch_bounds__(256, 2) void attn_kernel(
    const float* __restrict__ qkv, float* __restrict__ out)
{
    extern __shared__ float sm[];
    float* Qs = sm;
    float* Ks = sm + 64 * TS;
    float* Vs = sm + 2 * 64 * TS;
    float* Ps = Qs;

    const int tid = threadIdx.x;
    const int qt  = blockIdx.x;
    const int h   = blockIdx.y;
    const int b   = blockIdx.z;
    const int q0  = qt * 64;
    const size_t bhbase = (size_t)b * Sz * D3z + (size_t)h * HDz;

    for (int idx = tid; idx < 1024; idx += 256) {
        int r  = idx >> 4;
        int d4 = (idx & 15) << 2;
        float4 v = *(const float4*)(qkv + bhbase + (size_t)(q0 + r) * D3z + d4);
        float* q = Qs + r * TS + d4;
        q[0] = v.x * 0.125f; q[1] = v.y * 0.125f;
        q[2] = v.z * 0.125f; q[3] = v.w * 0.125f;
    }
    __syncthreads();

    const int i = tid >> 2;
    const int g = tid & 3;

    float4 qv[16];
    #pragma unroll
    for (int dw = 0; dw < 16; dw++)
        qv[dw] = *(const float4*)&Qs[i * TS + 4 * dw];

    float4 o0 = make_float4(0, 0, 0, 0), o1 = o0, o2 = o0, o3 = o0;
    float m = -__int_as_float(0x7f800000);
    float l = 0.f;

    for (int kt = 0; kt <= qt; kt++) {
        const int k0 = kt * 64;
        __syncthreads();
        for (int idx = tid; idx < 1024; idx += 256) {
            int r  = idx >> 4;
            int d4 = (idx & 15) << 2;
            const float* kp = qkv + bhbase + (size_t)(k0 + r) * D3z + Dz + d4;
            float4 kvv = *(const float4*)kp;
            float4 vvv = *(const float4*)(kp + Dz);
            *(float4*)&Ks[r * TS + d4] = kvv;
            *(float4*)&Vs[r * TS + d4] = vvv;
        }
        __syncthreads();

        float s[16];
        #pragma unroll
        for (int jj = 0; jj < 16; jj++) {
            const float4* kr = (const float4*)&Ks[(g + 4 * jj) * TS];
            float acc = 0.f;
            #pragma unroll
            for (int dw = 0; dw < 16; dw++) {
                float4 k4 = kr[dw];
                acc = fmaf(qv[dw].x, k4.x, acc);
                acc = fmaf(qv[dw].y, k4.y, acc);
                acc = fmaf(qv[dw].z, k4.z, acc);
                acc = fmaf(qv[dw].w, k4.w, acc);
            }
            s[jj] = acc;
        }

        if (kt == qt) {
            #pragma unroll
            for (int jj = 0; jj < 16; jj++)
                if (g + 4 * jj > i) s[jj] = -__int_as_float(0x7f800000);
        }

        float tmax = s[0];
        #pragma unroll
        for (int jj = 1; jj < 16; jj++) tmax = fmaxf(tmax, s[jj]);
        tmax = fmaxf(tmax, __shfl_xor_sync(0xffffffffu, tmax, 1));
        tmax = fmaxf(tmax, __shfl_xor_sync(0xffffffffu, tmax, 2));

        float newm  = fmaxf(m, tmax);
        float alpha = __expf(m - newm);
        float rsum = 0.f;
        #pragma unroll
        for (int jj = 0; jj < 16; jj++) {
            float p = __expf(s[jj] - newm);
            s[jj] = p;
            rsum += p;
        }
        rsum += __shfl_xor_sync(0xffffffffu, rsum, 1);
        rsum += __shfl_xor_sync(0xffffffffu, rsum, 2);
        m = newm;
        l = l * alpha + rsum;

        o0.x *= alpha; o0.y *= alpha; o0.z *= alpha; o0.w *= alpha;
        o1.x *= alpha; o1.y *= alpha; o1.z *= alpha; o1.w *= alpha;
        o2.x *= alpha; o2.y *= alpha; o2.z *= alpha; o2.w *= alpha;
        o3.x *= alpha; o3.y *= alpha; o3.z *= alpha; o3.w *= alpha;

        #pragma unroll
        for (int jj = 0; jj < 16; jj++)
            Ps[i * TS + g + 4 * jj] = s[jj];
        __syncthreads();

        #pragma unroll 8
        for (int j = 0; j < 64; j++) {
            float p = Ps[i * TS + j];
            const float4* vr = (const float4*)&Vs[j * TS + g * 16];
            float4 v0 = vr[0], v1 = vr[1], v2 = vr[2], v3 = vr[3];
            o0.x = fmaf(p, v0.x, o0.x); o0.y = fmaf(p, v0.y, o0.y);
            o0.z = fmaf(p, v0.z, o0.z); o0.w = fmaf(p, v0.w, o0.w);
            o1.x = fmaf(p, v1.x, o1.x); o1.y = fmaf(p, v1.y, o1.y);
            o1.z = fmaf(p, v1.z, o1.z); o1.w = fmaf(p, v1.w, o1.w);
            o2.x = fmaf(p, v2.x, o2.x); o2.y = fmaf(p, v2.y, o2.y);
            o2.z = fmaf(p, v2.z, o2.z); o2.w = fmaf(p, v2.w, o2.w);
            o3.x = fmaf(p, v3.x, o3.x); o3.y = fmaf(p, v3.y, o3.y);
            o3.z = fmaf(p, v3.z, o3.z); o3.w = fmaf(p, v3.w, o3.w);
        }
    }

    float inv = 1.f / l;
    o0.x *= inv; o0.y *= inv; o0.z *= inv; o0.w *= inv;
    o1.x *= inv; o1.y *= inv; o1.z *= inv; o1.w *= inv;
    o2.x *= inv; o2.y *= inv; o2.z *= inv; o2.w *= inv;
    o3.x *= inv; o3.y *= inv; o3.z *= inv; o3.w *= inv;

    float* op = out + (size_t)(b * Sz + q0 + i) * Dz + h * HDz + g * 16;
    *(float4*)op        = o0;
    *(float4*)(op + 4)  = o1;
    *(float4*)(op + 8)  = o2;
    *(float4*)(op + 12) = o3;
}

// ---------------------------------------------------------------------------
extern "C" void kernel_launch(void* const* d_in, const int* in_sizes, int n_in,
                              void* d_out, int out_size)
{
    const float* x      = (const float*)d_in[0];
    const float* w_qkv  = (const float*)d_in[1];
    const float* w_proj = (const float*)d_in[2];
    float* out = (float*)d_out;

    void *qkvp, *attnp, *xp, *wqp, *wpp;
    cudaGetSymbolAddress(&qkvp, g_qkv);
    cudaGetSymbolAddress(&attnp, g_attn);
    cudaGetSymbolAddress(&xp, g_x);
    cudaGetSymbolAddress(&wqp, g_wq);
    cudaGetSymbolAddress(&wpp, g_wp);

    cudaFuncSetAttribute(attn_kernel,
                         cudaFuncAttributeMaxDynamicSharedMemorySize, ATT_SMEM);
    cudaFuncSetAttribute(gemm_mma_kernel,
                         cudaFuncAttributeMaxDynamicSharedMemorySize, GEMM_SMEM);

    const int M = Mz;

    // 0) tf32-round GEMM inputs
    cvt_tf32_kernel<<<(M * Dz / 4 + 255) / 256, 256>>>(x, (float*)xp, M * Dz / 4);
    cvt_tf32_kernel<<<(D3z * Dz / 4 + 255) / 256, 256>>>(w_qkv, (float*)wqp, D3z * Dz / 4);
    cvt_tf32_kernel<<<(Dz * Dz / 4 + 255) / 256, 256>>>(w_proj, (float*)wpp, Dz * Dz / 4);

    // 1) QKV projection (tensor cores): [8192,1024] x [3072,1024]^T
    gemm_mma_kernel<<<dim3(D3z / 128, M / 128), 256, GEMM_SMEM>>>(
        (const float*)xp, (const float*)wqp, (float*)qkvp, M, D3z, Dz);

    // 2) Causal flash attention -> g_attn [8192,1024]
    attn_kernel<<<dim3(Sz / 64, Hz, Bz), 256, ATT_SMEM>>>(
        (const float*)qkvp, (float*)attnp);

    // 2b) tf32-round attention output (in place) for the proj GEMM
    cvt_tf32_kernel<<<(M * Dz / 4 + 255) / 256, 256>>>(
        (const float*)attnp, (float*)attnp, M * Dz / 4);

    // 3) Output projection (tensor cores): [8192,1024] x [1024,1024]^T
    gemm_mma_kernel<<<dim3(Dz / 128, M / 128), 256, GEMM_SMEM>>>(
        (const float*)attnp, (const float*)wpp, out, M, Dz, Dz);
}

// round 4
// speedup vs baseline: 5.3936x; 4.2079x over previous
#include <cuda_runtime.h>
#include <cstdint>
#include <math.h>

// Problem constants
#define Bz 4
#define Sz 2048
#define Dz 1024
#define Hz 16
#define HDz 64
#define D3z 3072
#define Mz (Bz * Sz)

// Scratch (device globals: allocation-free per harness rules)
__device__ float g_qkv[(size_t)Mz * D3z];   // [8192, 3072]
__device__ float g_attn[(size_t)Mz * Dz];   // [8192, 1024]
__device__ float g_x[(size_t)Mz * Dz];      // tf32-rounded x
__device__ float g_wq[(size_t)D3z * Dz];    // tf32-rounded w_qkv
__device__ float g_wp[(size_t)Dz * Dz];     // tf32-rounded w_proj

// ---------------------------------------------------------------------------
// Helpers
// ---------------------------------------------------------------------------
__device__ __forceinline__ uint32_t smem_u32(const void* p) {
    uint32_t a;
    asm("{ .reg .u64 t; cvta.to.shared.u64 t, %1; cvt.u32.u64 %0, t; }"
        : "=r"(a) : "l"(p));
    return a;
}

__device__ __forceinline__ uint32_t f2tf32(float x) {
    uint32_t r;
    asm("cvt.rna.tf32.f32 %0, %1;" : "=r"(r) : "f"(x));
    return r;
}

#define CP_ASYNC16(dst, src) \
    asm volatile("cp.async.cg.shared.global [%0], [%1], 16;" \
        :: "r"((uint32_t)(dst)), "l"(src) : "memory")
#define CP_COMMIT() asm volatile("cp.async.commit_group;" ::: "memory")
#define CP_WAIT2() asm volatile("cp.async.wait_group 2;" ::: "memory")
#define CP_WAIT1() asm volatile("cp.async.wait_group 1;" ::: "memory")
#define CP_WAIT0() asm volatile("cp.async.wait_group 0;" ::: "memory")

// m16n8k8 tf32 MMA (sm_80+, valid at compute_103)
__device__ __forceinline__ void mma_tf32(
    float& d0, float& d1, float& d2, float& d3,
    uint32_t a0, uint32_t a1, uint32_t a2, uint32_t a3,
    uint32_t b0, uint32_t b1)
{
    asm volatile(
        "mma.sync.aligned.m16n8k8.row.col.f32.tf32.tf32.f32 "
        "{%0,%1,%2,%3}, {%4,%5,%6,%7}, {%8,%9}, {%0,%1,%2,%3};"
        : "+f"(d0), "+f"(d1), "+f"(d2), "+f"(d3)
        : "r"(a0), "r"(a1), "r"(a2), "r"(a3), "r"(b0), "r"(b1));
}

// ---------------------------------------------------------------------------
// tf32 round-to-nearest conversion (in 32-bit containers)
// ---------------------------------------------------------------------------
__global__ __launch_bounds__(256) void cvt_tf32_kernel(
    const float* __restrict__ in, float* __restrict__ out, int n4)
{
    int i = blockIdx.x * blockDim.x + threadIdx.x;
    if (i >= n4) return;
    float4 v = ((const float4*)in)[i];
    uint4 o;
    o.x = f2tf32(v.x); o.y = f2tf32(v.y);
    o.z = f2tf32(v.z); o.w = f2tf32(v.w);
    ((uint4*)out)[i] = o;
}

// ---------------------------------------------------------------------------
// tf32 mma.sync NT GEMM (unchanged from R3: passed, 385us QKV)
// ---------------------------------------------------------------------------
#define STAGES 4
#define BK 32
#define AST 36
#define STAGE_FLOATS (128 * AST * 2)
#define GEMM_SMEM (STAGES * STAGE_FLOATS * 4)

__global__ __launch_bounds__(256, 1)
void gemm_mma_kernel(const float* __restrict__ A, const float* __restrict__ B,
                     float* __restrict__ C, int M, int N, int K)
{
    extern __shared__ float smf[];
    uint32_t sb = smem_u32(smf);
    const int tid = threadIdx.x;
    const int wid = tid >> 5;
    const int l   = tid & 31;
    const int g   = l >> 2;
    const int tg  = l & 3;
    const int wm  = wid >> 1;
    const int wn  = wid & 1;
    const int m0  = blockIdx.y * 128;
    const int n0  = blockIdx.x * 128;
    const int nchunk = K / BK;

    auto issue = [&](int c, int s) {
        uint32_t sA = sb + (uint32_t)s * STAGE_FLOATS * 4;
        uint32_t sB = sA + 128u * AST * 4;
        const float* Ab = A + (size_t)m0 * K + c * BK;
        const float* Bb = B + (size_t)n0 * K + c * BK;
        #pragma unroll
        for (int i = 0; i < 4; i++) {
            int idx = tid + 256 * i;
            int row = idx >> 3;
            int c4  = idx & 7;
            uint32_t so = (uint32_t)(row * AST + c4 * 4) * 4;
            CP_ASYNC16(sA + so, Ab + (size_t)row * K + c4 * 4);
            CP_ASYNC16(sB + so, Bb + (size_t)row * K + c4 * 4);
        }
        CP_COMMIT();
    };

    float acc[2][8][4];
    #pragma unroll
    for (int mt = 0; mt < 2; mt++)
        #pragma unroll
        for (int nt = 0; nt < 8; nt++)
            #pragma unroll
            for (int q = 0; q < 4; q++) acc[mt][nt][q] = 0.f;

    #pragma unroll
    for (int s = 0; s < STAGES - 1; s++) issue(s, s);

    for (int c = 0; c < nchunk; c++) {
        int pa = nchunk - 1 - c;
        if (pa >= 2)      { CP_WAIT2(); }
        else if (pa == 1) { CP_WAIT1(); }
        else              { CP_WAIT0(); }
        __syncthreads();

        int cn = c + STAGES - 1;
        if (cn < nchunk) issue(cn, cn & (STAGES - 1));

        const float* As = smf + (size_t)(c & (STAGES - 1)) * STAGE_FLOATS;
        const float* Bs = As + 128 * AST;
        const uint32_t* Au = (const uint32_t*)As;
        const uint32_t* Bu = (const uint32_t*)Bs;

        #pragma unroll
        for (int s4 = 0; s4 < 4; s4++) {
            uint32_t a[2][4];
            #pragma unroll
            for (int mt = 0; mt < 2; mt++) {
                int base = (wm * 32 + mt * 16 + g) * AST + s4 * 8 + tg;
                a[mt][0] = Au[base];
                a[mt][1] = Au[base + 8 * AST];
                a[mt][2] = Au[base + 4];
                a[mt][3] = Au[base + 8 * AST + 4];
            }
            uint32_t b[8][2];
            #pragma unroll
            for (int nt = 0; nt < 8; nt++) {
                int base = (wn * 64 + nt * 8 + g) * AST + s4 * 8 + tg;
                b[nt][0] = Bu[base];
                b[nt][1] = Bu[base + 4];
            }
            #pragma unroll
            for (int mt = 0; mt < 2; mt++)
                #pragma unroll
                for (int nt = 0; nt < 8; nt++)
                    mma_tf32(acc[mt][nt][0], acc[mt][nt][1],
                             acc[mt][nt][2], acc[mt][nt][3],
                             a[mt][0], a[mt][1], a[mt][2], a[mt][3],
                             b[nt][0], b[nt][1]);
        }
    }

    #pragma unroll
    for (int mt = 0; mt < 2; mt++) {
        int r = m0 + wm * 32 + mt * 16 + g;
        #pragma unroll
        for (int nt = 0; nt < 8; nt++) {
            int cc = n0 + wn * 64 + nt * 8 + tg * 2;
            *(float2*)&C[(size_t)r * N + cc] =
                make_float2(acc[mt][nt][0], acc[mt][nt][1]);
            *(float2*)&C[(size_t)(r + 8) * N + cc] =
                make_float2(acc[mt][nt][2], acc[mt][nt][3]);
        }
    }
}

// ---------------------------------------------------------------------------
// Tensor-core flash attention (tf32 mma.sync).
// Block = 64 q-rows x (head, batch). 128 threads = 4 warps; warp owns 16 rows.
// Q as register A-frags. K: SMEM stride 68 (conflict-free B-frag LDS).
// V: SMEM stride 72 (conflict-free B-frag LDS). P: per-warp SMEM rows, str 68.
// ---------------------------------------------------------------------------
#define KST 68
#define VST 72
#define PST 68
#define ATT_SMEM ((64 * KST + 64 * VST + 64 * PST) * 4)   // 53248 bytes

__global__ __launch_bounds__(128, 3) void attn_mma_kernel(
    const float* __restrict__ qkv, float* __restrict__ out)
{
    extern __shared__ float sm[];
    float* Ks = sm;
    float* Vs = sm + 64 * KST;
    float* Ps = sm + 64 * KST + 64 * VST;
    uint32_t* Ku = (uint32_t*)Ks;
    uint32_t* Vu = (uint32_t*)Vs;
    uint32_t* Pu = (uint32_t*)Ps;

    const int tid = threadIdx.x;
    const int w  = tid >> 5;
    const int l  = tid & 31;
    const int g  = l >> 2;
    const int tg = l & 3;
    const int qt = blockIdx.x;
    const int h  = blockIdx.y;
    const int b  = blockIdx.z;
    const int q0 = qt * 64;
    const size_t bh = (size_t)b * Sz * D3z + (size_t)h * HDz;
    const float NEG_INF = -__int_as_float(0x7f800000);

    // Stage Q (scaled by 1/8, tf32-rounded) into Ps
    for (int idx = tid; idx < 1024; idx += 128) {
        int r = idx >> 4, c4 = (idx & 15) << 2;
        float4 v = *(const float4*)(qkv + bh + (size_t)(q0 + r) * D3z + c4);
        uint4 o4;
        o4.x = f2tf32(v.x * 0.125f); o4.y = f2tf32(v.y * 0.125f);
        o4.z = f2tf32(v.z * 0.125f); o4.w = f2tf32(v.w * 0.125f);
        *(uint4*)&Pu[r * PST + c4] = o4;
    }
    __syncthreads();

    // Q A-fragments (warp-private rows; Ps rows [w*16, w*16+16) are only ever
    // touched by warp w from here on)
    uint32_t qa[8][4];
    const int pr0 = (w * 16 + g) * PST;
    const int pr1 = (w * 16 + g + 8) * PST;
    #pragma unroll
    for (int kk = 0; kk < 8; kk++) {
        qa[kk][0] = Pu[pr0 + kk * 8 + tg];
        qa[kk][1] = Pu[pr1 + kk * 8 + tg];
        qa[kk][2] = Pu[pr0 + kk * 8 + tg + 4];
        qa[kk][3] = Pu[pr1 + kk * 8 + tg + 4];
    }

    float o[8][4];
    #pragma unroll
    for (int nt = 0; nt < 8; nt++)
        #pragma unroll
        for (int q = 0; q < 4; q++) o[nt][q] = 0.f;
    float m0 = NEG_INF, m1 = NEG_INF, l0 = 0.f, l1 = 0.f;

    for (int kt = 0; kt <= qt; kt++) {
        __syncthreads();   // previous iteration's K/V readers done
        for (int idx = tid; idx < 1024; idx += 128) {
            int r = idx >> 4, c4 = (idx & 15) << 2;
            const float* p = qkv + bh + (size_t)(kt * 64 + r) * D3z + Dz + c4;
            float4 kv = *(const float4*)p;
            float4 vv = *(const float4*)(p + Dz);
            uint4 k4, v4;
            k4.x = f2tf32(kv.x); k4.y = f2tf32(kv.y);
            k4.z = f2tf32(kv.z); k4.w = f2tf32(kv.w);
            v4.x = f2tf32(vv.x); v4.y = f2tf32(vv.y);
            v4.z = f2tf32(vv.z); v4.w = f2tf32(vv.w);
            *(uint4*)&Ku[r * KST + c4] = k4;
            *(uint4*)&Vu[r * VST + c4] = v4;
        }
        __syncthreads();

        // Scores S = Q K^T  (S[i][j], B-frag: b0 = K[nt*8+g][kk*8+tg])
        float s[8][4];
        #pragma unroll
        for (int nt = 0; nt < 8; nt++)
            #pragma unroll
            for (int q = 0; q < 4; q++) s[nt][q] = 0.f;

        #pragma unroll
        for (int kk = 0; kk < 8; kk++) {
            #pragma unroll
            for (int nt = 0; nt < 8; nt++) {
                int kb = (nt * 8 + g) * KST + kk * 8 + tg;
                uint32_t b0 = Ku[kb];
                uint32_t b1 = Ku[kb + 4];
                mma_tf32(s[nt][0], s[nt][1], s[nt][2], s[nt][3],
                         qa[kk][0], qa[kk][1], qa[kk][2], qa[kk][3], b0, b1);
            }
        }

        if (kt == qt) {   // causal mask in diagonal tile (local i vs local j)
            int i0 = w * 16 + g, i1 = i0 + 8;
            #pragma unroll
            for (int nt = 0; nt < 8; nt++) {
                int j0 = nt * 8 + 2 * tg;
                if (j0     > i0) s[nt][0] = NEG_INF;
                if (j0 + 1 > i0) s[nt][1] = NEG_INF;
                if (j0     > i1) s[nt][2] = NEG_INF;
                if (j0 + 1 > i1) s[nt][3] = NEG_INF;
            }
        }

        // Online softmax (rows g and g+8; reduce over quad lanes xor1/xor2)
        float r0 = NEG_INF, r1 = NEG_INF;
        #pragma unroll
        for (int nt = 0; nt < 8; nt++) {
            r0 = fmaxf(r0, fmaxf(s[nt][0], s[nt][1]));
            r1 = fmaxf(r1, fmaxf(s[nt][2], s[nt][3]));
        }
        r0 = fmaxf(r0, __shfl_xor_sync(0xffffffffu, r0, 1));
        r0 = fmaxf(r0, __shfl_xor_sync(0xffffffffu, r0, 2));
        r1 = fmaxf(r1, __shfl_xor_sync(0xffffffffu, r1, 1));
        r1 = fmaxf(r1, __shfl_xor_sync(0xffffffffu, r1, 2));

        float nm0 = fmaxf(m0, r0), nm1 = fmaxf(m1, r1);
        float a0 = __expf(m0 - nm0), a1 = __expf(m1 - nm1);
        float sum0 = 0.f, sum1 = 0.f;
        #pragma unroll
        for (int nt = 0; nt < 8; nt++) {
            s[nt][0] = __expf(s[nt][0] - nm0);
            s[nt][1] = __expf(s[nt][1] - nm0);
            s[nt][2] = __expf(s[nt][2] - nm1);
            s[nt][3] = __expf(s[nt][3] - nm1);
            sum0 += s[nt][0] + s[nt][1];
            sum1 += s[nt][2] + s[nt][3];
        }
        sum0 += __shfl_xor_sync(0xffffffffu, sum0, 1);
        sum0 += __shfl_xor_sync(0xffffffffu, sum0, 2);
        sum1 += __shfl_xor_sync(0xffffffffu, sum1, 1);
        sum1 += __shfl_xor_sync(0xffffffffu, sum1, 2);
        m0 = nm0; m1 = nm1;
        l0 = l0 * a0 + sum0;
        l1 = l1 * a1 + sum1;

        #pragma unroll
        for (int nt = 0; nt < 8; nt++) {
            o[nt][0] *= a0; o[nt][1] *= a0;
            o[nt][2] *= a1; o[nt][3] *= a1;
        }

        // Store P (tf32) to warp-private Ps rows
        #pragma unroll
        for (int nt = 0; nt < 8; nt++) {
            int c0 = nt * 8 + 2 * tg;
            Pu[pr0 + c0]     = f2tf32(s[nt][0]);
            Pu[pr0 + c0 + 1] = f2tf32(s[nt][1]);
            Pu[pr1 + c0]     = f2tf32(s[nt][2]);
            Pu[pr1 + c0 + 1] = f2tf32(s[nt][3]);
        }
        __syncwarp();

        // O += P V   (A-frag from Ps; B-frag b0 = V[kk*8+tg][nt*8+g])
        #pragma unroll
        for (int kk = 0; kk < 8; kk++) {
            uint32_t pa0 = Pu[pr0 + kk * 8 + tg];
            uint32_t pa1 = Pu[pr1 + kk * 8 + tg];
            uint32_t pa2 = Pu[pr0 + kk * 8 + tg + 4];
            uint32_t pa3 = Pu[pr1 + kk * 8 + tg + 4];
            #pragma unroll
            for (int nt = 0; nt < 8; nt++) {
                uint32_t b0 = Vu[(kk * 8 + tg) * VST + nt * 8 + g];
                uint32_t b1 = Vu[(kk * 8 + tg + 4) * VST + nt * 8 + g];
                mma_tf32(o[nt][0], o[nt][1], o[nt][2], o[nt][3],
                         pa0, pa1, pa2, pa3, b0, b1);
            }
        }
    }

    float i0v = 1.f / l0, i1v = 1.f / l1;
    float* o0p = out + (size_t)(b * Sz + q0 + w * 16 + g) * Dz + h * HDz;
    float* o1p = o0p + (size_t)8 * Dz;
    #pragma unroll
    for (int nt = 0; nt < 8; nt++) {
        int cc = nt * 8 + 2 * tg;
        *(float2*)(o0p + cc) = make_float2(o[nt][0] * i0v, o[nt][1] * i0v);
        *(float2*)(o1p + cc) = make_float2(o[nt][2] * i1v, o[nt][3] * i1v);
    }
}

// ---------------------------------------------------------------------------
extern "C" void kernel_launch(void* const* d_in, const int* in_sizes, int n_in,
                              void* d_out, int out_size)
{
    const float* x      = (const float*)d_in[0];
    const float* w_qkv  = (const float*)d_in[1];
    const float* w_proj = (const float*)d_in[2];
    float* out = (float*)d_out;

    void *qkvp, *attnp, *xp, *wqp, *wpp;
    cudaGetSymbolAddress(&qkvp, g_qkv);
    cudaGetSymbolAddress(&attnp, g_attn);
    cudaGetSymbolAddress(&xp, g_x);
    cudaGetSymbolAddress(&wqp, g_wq);
    cudaGetSymbolAddress(&wpp, g_wp);

    cudaFuncSetAttribute(attn_mma_kernel,
                         cudaFuncAttributeMaxDynamicSharedMemorySize, ATT_SMEM);
    cudaFuncSetAttribute(gemm_mma_kernel,
                         cudaFuncAttributeMaxDynamicSharedMemorySize, GEMM_SMEM);

    const int M = Mz;

    // 0) tf32-round GEMM inputs
    cvt_tf32_kernel<<<(M * Dz / 4 + 255) / 256, 256>>>(x, (float*)xp, M * Dz / 4);
    cvt_tf32_kernel<<<(D3z * Dz / 4 + 255) / 256, 256>>>(w_qkv, (float*)wqp, D3z * Dz / 4);
    cvt_tf32_kernel<<<(Dz * Dz / 4 + 255) / 256, 256>>>(w_proj, (float*)wpp, Dz * Dz / 4);

    // 1) QKV projection (tensor cores): [8192,1024] x [3072,1024]^T
    gemm_mma_kernel<<<dim3(D3z / 128, M / 128), 256, GEMM_SMEM>>>(
        (const float*)xp, (const float*)wqp, (float*)qkvp, M, D3z, Dz);

    // 2) Causal flash attention (tensor cores) -> g_attn
    attn_mma_kernel<<<dim3(Sz / 64, Hz, Bz), 128, ATT_SMEM>>>(
        (const float*)qkvp, (float*)attnp);

    // 2b) tf32-round attention output (in place) for the proj GEMM
    cvt_tf32_kernel<<<(M * Dz / 4 + 255) / 256, 256>>>(
        (const float*)attnp, (float*)attnp, M * Dz / 4);

    // 3) Output projection (tensor cores): [8192,1024] x [1024,1024]^T
    gemm_mma_kernel<<<dim3(Dz / 128, M / 128), 256, GEMM_SMEM>>>(
        (const float*)attnp, (const float*)wpp, out, M, Dz, Dz);
}

// round 5
// speedup vs baseline: 5.9135x; 1.0964x over previous
#include <cuda_runtime.h>
#include <cstdint>
#include <math.h>

// Problem constants
#define Bz 4
#define Sz 2048
#define Dz 1024
#define Hz 16
#define HDz 64
#define D3z 3072
#define Mz (Bz * Sz)

// Scratch (device globals: allocation-free per harness rules)
__device__ float g_qkv[(size_t)Mz * D3z];   // [8192, 3072]
__device__ float g_attn[(size_t)Mz * Dz];   // [8192, 1024] (tf32-rounded)
__device__ float g_x[(size_t)Mz * Dz];      // tf32-rounded x
__device__ float g_wq[(size_t)D3z * Dz];    // tf32-rounded w_qkv
__device__ float g_wp[(size_t)Dz * Dz];     // tf32-rounded w_proj

// ---------------------------------------------------------------------------
// Helpers
// ---------------------------------------------------------------------------
__device__ __forceinline__ uint32_t smem_u32(const void* p) {
    uint32_t a;
    asm("{ .reg .u64 t; cvta.to.shared.u64 t, %1; cvt.u32.u64 %0, t; }"
        : "=r"(a) : "l"(p));
    return a;
}

__device__ __forceinline__ uint32_t f2tf32(float x) {
    uint32_t r;
    asm("cvt.rna.tf32.f32 %0, %1;" : "=r"(r) : "f"(x));
    return r;
}

#define CP_ASYNC16(dst, src) \
    asm volatile("cp.async.cg.shared.global [%0], [%1], 16;" \
        :: "r"((uint32_t)(dst)), "l"(src) : "memory")
#define CP_COMMIT() asm volatile("cp.async.commit_group;" ::: "memory")
#define CP_WAIT1() asm volatile("cp.async.wait_group 1;" ::: "memory")
#define CP_WAIT0() asm volatile("cp.async.wait_group 0;" ::: "memory")

// m16n8k8 tf32 MMA (sm_80+, valid at compute_103)
__device__ __forceinline__ void mma_tf32(
    float& d0, float& d1, float& d2, float& d3,
    uint32_t a0, uint32_t a1, uint32_t a2, uint32_t a3,
    uint32_t b0, uint32_t b1)
{
    asm volatile(
        "mma.sync.aligned.m16n8k8.row.col.f32.tf32.tf32.f32 "
        "{%0,%1,%2,%3}, {%4,%5,%6,%7}, {%8,%9}, {%0,%1,%2,%3};"
        : "+f"(d0), "+f"(d1), "+f"(d2), "+f"(d3)
        : "r"(a0), "r"(a1), "r"(a2), "r"(a3), "r"(b0), "r"(b1));
}

// ---------------------------------------------------------------------------
// tf32 round-to-nearest conversion (in 32-bit containers)
// ---------------------------------------------------------------------------
__global__ __launch_bounds__(256) void cvt_tf32_kernel(
    const float* __restrict__ in, float* __restrict__ out, int n4)
{
    int i = blockIdx.x * blockDim.x + threadIdx.x;
    if (i >= n4) return;
    float4 v = ((const float4*)in)[i];
    uint4 o;
    o.x = f2tf32(v.x); o.y = f2tf32(v.y);
    o.z = f2tf32(v.z); o.w = f2tf32(v.w);
    ((uint4*)out)[i] = o;
}

// ---------------------------------------------------------------------------
// tf32 mma.sync NT GEMM. 128x128 CTA, BK=32, 8 warps (4Mx2N, warp tile 32x64).
// 3-stage cp.async pipeline (110.6KB SMEM) + 128-reg cap -> 2 CTAs/SM.
// ---------------------------------------------------------------------------
#define STAGES 3
#define BK 32
#define AST 36
#define STAGE_FLOATS (128 * AST * 2)
#define GEMM_SMEM (STAGES * STAGE_FLOATS * 4)   // 110592 bytes

__global__ __launch_bounds__(256, 2)
void gemm_mma_kernel(const float* __restrict__ A, const float* __restrict__ B,
                     float* __restrict__ C, int M, int N, int K)
{
    extern __shared__ float smf[];
    uint32_t sb = smem_u32(smf);
    const int tid = threadIdx.x;
    const int wid = tid >> 5;
    const int l   = tid & 31;
    const int g   = l >> 2;
    const int tg  = l & 3;
    const int wm  = wid >> 1;
    const int wn  = wid & 1;
    const int m0  = blockIdx.y * 128;
    const int n0  = blockIdx.x * 128;
    const int nchunk = K / BK;

    auto issue = [&](int c, int s) {
        uint32_t sA = sb + (uint32_t)s * STAGE_FLOATS * 4;
        uint32_t sB = sA + 128u * AST * 4;
        const float* Ab = A + (size_t)m0 * K + c * BK;
        const float* Bb = B + (size_t)n0 * K + c * BK;
        #pragma unroll
        for (int i = 0; i < 4; i++) {
            int idx = tid + 256 * i;
            int row = idx >> 3;
            int c4  = idx & 7;
            uint32_t so = (uint32_t)(row * AST + c4 * 4) * 4;
            CP_ASYNC16(sA + so, Ab + (size_t)row * K + c4 * 4);
            CP_ASYNC16(sB + so, Bb + (size_t)row * K + c4 * 4);
        }
        CP_COMMIT();
    };

    float acc[2][8][4];
    #pragma unroll
    for (int mt = 0; mt < 2; mt++)
        #pragma unroll
        for (int nt = 0; nt < 8; nt++)
            #pragma unroll
            for (int q = 0; q < 4; q++) acc[mt][nt][q] = 0.f;

    #pragma unroll
    for (int s = 0; s < STAGES - 1; s++) issue(s, s);

    for (int c = 0; c < nchunk; c++) {
        if (c < nchunk - 1) { CP_WAIT1(); } else { CP_WAIT0(); }
        __syncthreads();

        int cn = c + STAGES - 1;
        if (cn < nchunk) issue(cn, cn % STAGES);

        const float* As = smf + (size_t)(c % STAGES) * STAGE_FLOATS;
        const float* Bs = As + 128 * AST;
        const uint32_t* Au = (const uint32_t*)As;
        const uint32_t* Bu = (const uint32_t*)Bs;

        #pragma unroll
        for (int s4 = 0; s4 < 4; s4++) {
            uint32_t a[2][4];
            #pragma unroll
            for (int mt = 0; mt < 2; mt++) {
                int base = (wm * 32 + mt * 16 + g) * AST + s4 * 8 + tg;
                a[mt][0] = Au[base];
                a[mt][1] = Au[base + 8 * AST];
                a[mt][2] = Au[base + 4];
                a[mt][3] = Au[base + 8 * AST + 4];
            }
            uint32_t b[8][2];
            #pragma unroll
            for (int nt = 0; nt < 8; nt++) {
                int base = (wn * 64 + nt * 8 + g) * AST + s4 * 8 + tg;
                b[nt][0] = Bu[base];
                b[nt][1] = Bu[base + 4];
            }
            #pragma unroll
            for (int mt = 0; mt < 2; mt++)
                #pragma unroll
                for (int nt = 0; nt < 8; nt++)
                    mma_tf32(acc[mt][nt][0], acc[mt][nt][1],
                             acc[mt][nt][2], acc[mt][nt][3],
                             a[mt][0], a[mt][1], a[mt][2], a[mt][3],
                             b[nt][0], b[nt][1]);
        }
    }

    #pragma unroll
    for (int mt = 0; mt < 2; mt++) {
        int r = m0 + wm * 32 + mt * 16 + g;
        #pragma unroll
        for (int nt = 0; nt < 8; nt++) {
            int cc = n0 + wn * 64 + nt * 8 + tg * 2;
            *(float2*)&C[(size_t)r * N + cc] =
                make_float2(acc[mt][nt][0], acc[mt][nt][1]);
            *(float2*)&C[(size_t)(r + 8) * N + cc] =
                make_float2(acc[mt][nt][2], acc[mt][nt][3]);
        }
    }
}

// ---------------------------------------------------------------------------
// Tensor-core flash attention (tf32 mma.sync). Unchanged core from R4;
// epilogue now emits tf32-rounded values (feeds proj GEMM directly).
// ---------------------------------------------------------------------------
#define KST 68
#define VST 72
#define PST 68
#define ATT_SMEM ((64 * KST + 64 * VST + 64 * PST) * 4)   // 53248 bytes

__global__ __launch_bounds__(128, 3) void attn_mma_kernel(
    const float* __restrict__ qkv, float* __restrict__ out)
{
    extern __shared__ float sm[];
    float* Ks = sm;
    float* Vs = sm + 64 * KST;
    float* Ps = sm + 64 * KST + 64 * VST;
    uint32_t* Ku = (uint32_t*)Ks;
    uint32_t* Vu = (uint32_t*)Vs;
    uint32_t* Pu = (uint32_t*)Ps;

    const int tid = threadIdx.x;
    const int w  = tid >> 5;
    const int l  = tid & 31;
    const int g  = l >> 2;
    const int tg = l & 3;
    const int qt = blockIdx.x;
    const int h  = blockIdx.y;
    const int b  = blockIdx.z;
    const int q0 = qt * 64;
    const size_t bh = (size_t)b * Sz * D3z + (size_t)h * HDz;
    const float NEG_INF = -__int_as_float(0x7f800000);

    // Stage Q (scaled by 1/8, tf32-rounded) into Ps
    for (int idx = tid; idx < 1024; idx += 128) {
        int r = idx >> 4, c4 = (idx & 15) << 2;
        float4 v = *(const float4*)(qkv + bh + (size_t)(q0 + r) * D3z + c4);
        uint4 o4;
        o4.x = f2tf32(v.x * 0.125f); o4.y = f2tf32(v.y * 0.125f);
        o4.z = f2tf32(v.z * 0.125f); o4.w = f2tf32(v.w * 0.125f);
        *(uint4*)&Pu[r * PST + c4] = o4;
    }
    __syncthreads();

    uint32_t qa[8][4];
    const int pr0 = (w * 16 + g) * PST;
    const int pr1 = (w * 16 + g + 8) * PST;
    #pragma unroll
    for (int kk = 0; kk < 8; kk++) {
        qa[kk][0] = Pu[pr0 + kk * 8 + tg];
        qa[kk][1] = Pu[pr1 + kk * 8 + tg];
        qa[kk][2] = Pu[pr0 + kk * 8 + tg + 4];
        qa[kk][3] = Pu[pr1 + kk * 8 + tg + 4];
    }

    float o[8][4];
    #pragma unroll
    for (int nt = 0; nt < 8; nt++)
        #pragma unroll
        for (int q = 0; q < 4; q++) o[nt][q] = 0.f;
    float m0 = NEG_INF, m1 = NEG_INF, l0 = 0.f, l1 = 0.f;

    for (int kt = 0; kt <= qt; kt++) {
        __syncthreads();
        for (int idx = tid; idx < 1024; idx += 128) {
            int r = idx >> 4, c4 = (idx & 15) << 2;
            const float* p = qkv + bh + (size_t)(kt * 64 + r) * D3z + Dz + c4;
            float4 kv = *(const float4*)p;
            float4 vv = *(const float4*)(p + Dz);
            uint4 k4, v4;
            k4.x = f2tf32(kv.x); k4.y = f2tf32(kv.y);
            k4.z = f2tf32(kv.z); k4.w = f2tf32(kv.w);
            v4.x = f2tf32(vv.x); v4.y = f2tf32(vv.y);
            v4.z = f2tf32(vv.z); v4.w = f2tf32(vv.w);
            *(uint4*)&Ku[r * KST + c4] = k4;
            *(uint4*)&Vu[r * VST + c4] = v4;
        }
        __syncthreads();

        float s[8][4];
        #pragma unroll
        for (int nt = 0; nt < 8; nt++)
            #pragma unroll
            for (int q = 0; q < 4; q++) s[nt][q] = 0.f;

        #pragma unroll
        for (int kk = 0; kk < 8; kk++) {
            #pragma unroll
            for (int nt = 0; nt < 8; nt++) {
                int kb = (nt * 8 + g) * KST + kk * 8 + tg;
                uint32_t b0 = Ku[kb];
                uint32_t b1 = Ku[kb + 4];
                mma_tf32(s[nt][0], s[nt][1], s[nt][2], s[nt][3],
                         qa[kk][0], qa[kk][1], qa[kk][2], qa[kk][3], b0, b1);
            }
        }

        if (kt == qt) {
            int i0 = w * 16 + g, i1 = i0 + 8;
            #pragma unroll
            for (int nt = 0; nt < 8; nt++) {
                int j0 = nt * 8 + 2 * tg;
                if (j0     > i0) s[nt][0] = NEG_INF;
                if (j0 + 1 > i0) s[nt][1] = NEG_INF;
                if (j0     > i1) s[nt][2] = NEG_INF;
                if (j0 + 1 > i1) s[nt][3] = NEG_INF;
            }
        }

        float r0 = NEG_INF, r1 = NEG_INF;
        #pragma unroll
        for (int nt = 0; nt < 8; nt++) {
            r0 = fmaxf(r0, fmaxf(s[nt][0], s[nt][1]));
            r1 = fmaxf(r1, fmaxf(s[nt][2], s[nt][3]));
        }
        r0 = fmaxf(r0, __shfl_xor_sync(0xffffffffu, r0, 1));
        r0 = fmaxf(r0, __shfl_xor_sync(0xffffffffu, r0, 2));
        r1 = fmaxf(r1, __shfl_xor_sync(0xffffffffu, r1, 1));
        r1 = fmaxf(r1, __shfl_xor_sync(0xffffffffu, r1, 2));

        float nm0 = fmaxf(m0, r0), nm1 = fmaxf(m1, r1);
        float a0 = __expf(m0 - nm0), a1 = __expf(m1 - nm1);
        float sum0 = 0.f, sum1 = 0.f;
        #pragma unroll
        for (int nt = 0; nt < 8; nt++) {
            s[nt][0] = __expf(s[nt][0] - nm0);
            s[nt][1] = __expf(s[nt][1] - nm0);
            s[nt][2] = __expf(s[nt][2] - nm1);
            s[nt][3] = __expf(s[nt][3] - nm1);
            sum0 += s[nt][0] + s[nt][1];
            sum1 += s[nt][2] + s[nt][3];
        }
        sum0 += __shfl_xor_sync(0xffffffffu, sum0, 1);
        sum0 += __shfl_xor_sync(0xffffffffu, sum0, 2);
        sum1 += __shfl_xor_sync(0xffffffffu, sum1, 1);
        sum1 += __shfl_xor_sync(0xffffffffu, sum1, 2);
        m0 = nm0; m1 = nm1;
        l0 = l0 * a0 + sum0;
        l1 = l1 * a1 + sum1;

        #pragma unroll
        for (int nt = 0; nt < 8; nt++) {
            o[nt][0] *= a0; o[nt][1] *= a0;
            o[nt][2] *= a1; o[nt][3] *= a1;
        }

        #pragma unroll
        for (int nt = 0; nt < 8; nt++) {
            int c0 = nt * 8 + 2 * tg;
            Pu[pr0 + c0]     = f2tf32(s[nt][0]);
            Pu[pr0 + c0 + 1] = f2tf32(s[nt][1]);
            Pu[pr1 + c0]     = f2tf32(s[nt][2]);
            Pu[pr1 + c0 + 1] = f2tf32(s[nt][3]);
        }
        __syncwarp();

        #pragma unroll
        for (int kk = 0; kk < 8; kk++) {
            uint32_t pa0 = Pu[pr0 + kk * 8 + tg];
            uint32_t pa1 = Pu[pr1 + kk * 8 + tg];
            uint32_t pa2 = Pu[pr0 + kk * 8 + tg + 4];
            uint32_t pa3 = Pu[pr1 + kk * 8 + tg + 4];
            #pragma unroll
            for (int nt = 0; nt < 8; nt++) {
                uint32_t b0 = Vu[(kk * 8 + tg) * VST + nt * 8 + g];
                uint32_t b1 = Vu[(kk * 8 + tg + 4) * VST + nt * 8 + g];
                mma_tf32(o[nt][0], o[nt][1], o[nt][2], o[nt][3],
                         pa0, pa1, pa2, pa3, b0, b1);
            }
        }
    }

    // Epilogue: scale by 1/l and round to tf32 (feeds proj GEMM directly)
    float i0v = 1.f / l0, i1v = 1.f / l1;
    uint32_t* o0p = (uint32_t*)(out + (size_t)(b * Sz + q0 + w * 16 + g) * Dz + h * HDz);
    uint32_t* o1p = o0p + (size_t)8 * Dz;
    #pragma unroll
    for (int nt = 0; nt < 8; nt++) {
        int cc = nt * 8 + 2 * tg;
        uint2 v0 = make_uint2(f2tf32(o[nt][0] * i0v), f2tf32(o[nt][1] * i0v));
        uint2 v1 = make_uint2(f2tf32(o[nt][2] * i1v), f2tf32(o[nt][3] * i1v));
        *(uint2*)(o0p + cc) = v0;
        *(uint2*)(o1p + cc) = v1;
    }
}

// ---------------------------------------------------------------------------
extern "C" void kernel_launch(void* const* d_in, const int* in_sizes, int n_in,
                              void* d_out, int out_size)
{
    const float* x      = (const float*)d_in[0];
    const float* w_qkv  = (const float*)d_in[1];
    const float* w_proj = (const float*)d_in[2];
    float* out = (float*)d_out;

    void *qkvp, *attnp, *xp, *wqp, *wpp;
    cudaGetSymbolAddress(&qkvp, g_qkv);
    cudaGetSymbolAddress(&attnp, g_attn);
    cudaGetSymbolAddress(&xp, g_x);
    cudaGetSymbolAddress(&wqp, g_wq);
    cudaGetSymbolAddress(&wpp, g_wp);

    cudaFuncSetAttribute(attn_mma_kernel,
                         cudaFuncAttributeMaxDynamicSharedMemorySize, ATT_SMEM);
    cudaFuncSetAttribute(gemm_mma_kernel,
                         cudaFuncAttributeMaxDynamicSharedMemorySize, GEMM_SMEM);

    const int M = Mz;

    // 0) tf32-round GEMM inputs
    cvt_tf32_kernel<<<(M * Dz / 4 + 255) / 256, 256>>>(x, (float*)xp, M * Dz / 4);
    cvt_tf32_kernel<<<(D3z * Dz / 4 + 255) / 256, 256>>>(w_qkv, (float*)wqp, D3z * Dz / 4);
    cvt_tf32_kernel<<<(Dz * Dz / 4 + 255) / 256, 256>>>(w_proj, (float*)wpp, Dz * Dz / 4);

    // 1) QKV projection (tensor cores): [8192,1024] x [3072,1024]^T
    gemm_mma_kernel<<<dim3(D3z / 128, M / 128), 256, GEMM_SMEM>>>(
        (const float*)xp, (const float*)wqp, (float*)qkvp, M, D3z, Dz);

    // 2) Causal flash attention (tensor cores) -> g_attn (tf32-rounded)
    attn_mma_kernel<<<dim3(Sz / 64, Hz, Bz), 128, ATT_SMEM>>>(
        (const float*)qkvp, (float*)attnp);

    // 3) Output projection (tensor cores): [8192,1024] x [1024,1024]^T
    gemm_mma_kernel<<<dim3(Dz / 128, M / 128), 256, GEMM_SMEM>>>(
        (const float*)attnp, (const float*)wpp, out, M, Dz, Dz);
}

// round 6
// speedup vs baseline: 5.9339x; 1.0035x over previous
#include <cuda_runtime.h>
#include <cstdint>
#include <math.h>

// Problem constants
#define Bz 4
#define Sz 2048
#define Dz 1024
#define Hz 16
#define HDz 64
#define D3z 3072
#define Mz (Bz * Sz)

// Scratch (device globals: allocation-free per harness rules)
__device__ float g_qkv[(size_t)Mz * D3z];   // [8192, 3072]
__device__ float g_attn[(size_t)Mz * Dz];   // [8192, 1024] (tf32-rounded)
__device__ float g_x[(size_t)Mz * Dz];      // tf32-rounded x
__device__ float g_wq[(size_t)D3z * Dz];    // tf32-rounded w_qkv
__device__ float g_wp[(size_t)Dz * Dz];     // tf32-rounded w_proj

// ---------------------------------------------------------------------------
// Helpers
// ---------------------------------------------------------------------------
__device__ __forceinline__ uint32_t smem_u32(const void* p) {
    uint32_t a;
    asm("{ .reg .u64 t; cvta.to.shared.u64 t, %1; cvt.u32.u64 %0, t; }"
        : "=r"(a) : "l"(p));
    return a;
}

__device__ __forceinline__ uint32_t f2tf32(float x) {
    uint32_t r;
    asm("cvt.rna.tf32.f32 %0, %1;" : "=r"(r) : "f"(x));
    return r;
}

#define CP_ASYNC16(dst, src) \
    asm volatile("cp.async.cg.shared.global [%0], [%1], 16;" \
        :: "r"((uint32_t)(dst)), "l"(src) : "memory")
#define CP_COMMIT() asm volatile("cp.async.commit_group;" ::: "memory")
#define CP_WAIT1() asm volatile("cp.async.wait_group 1;" ::: "memory")
#define CP_WAIT0() asm volatile("cp.async.wait_group 0;" ::: "memory")

// m16n8k8 tf32 MMA (sm_80+, valid at compute_103)
__device__ __forceinline__ void mma_tf32(
    float& d0, float& d1, float& d2, float& d3,
    uint32_t a0, uint32_t a1, uint32_t a2, uint32_t a3,
    uint32_t b0, uint32_t b1)
{
    asm volatile(
        "mma.sync.aligned.m16n8k8.row.col.f32.tf32.tf32.f32 "
        "{%0,%1,%2,%3}, {%4,%5,%6,%7}, {%8,%9}, {%0,%1,%2,%3};"
        : "+f"(d0), "+f"(d1), "+f"(d2), "+f"(d3)
        : "r"(a0), "r"(a1), "r"(a2), "r"(a3), "r"(b0), "r"(b1));
}

// ---------------------------------------------------------------------------
// Single fused tf32 rounding pass over x, w_qkv, w_proj
// ---------------------------------------------------------------------------
#define N4_X  (Mz * Dz / 4)      // 2097152
#define N4_WQ (D3z * Dz / 4)     // 786432
#define N4_WP (Dz * Dz / 4)      // 262144

__global__ __launch_bounds__(256) void cvt_all_kernel(
    const float* __restrict__ x,  float* __restrict__ xo,
    const float* __restrict__ wq, float* __restrict__ wqo,
    const float* __restrict__ wp, float* __restrict__ wpo)
{
    int i = blockIdx.x * blockDim.x + threadIdx.x;
    const float4* src;
    uint4* dst;
    int j;
    if (i < N4_X)                { src = (const float4*)x;  dst = (uint4*)xo;  j = i; }
    else if (i < N4_X + N4_WQ)   { src = (const float4*)wq; dst = (uint4*)wqo; j = i - N4_X; }
    else if (i < N4_X + N4_WQ + N4_WP)
                                 { src = (const float4*)wp; dst = (uint4*)wpo; j = i - N4_X - N4_WQ; }
    else return;
    float4 v = src[j];
    uint4 o;
    o.x = f2tf32(v.x); o.y = f2tf32(v.y);
    o.z = f2tf32(v.z); o.w = f2tf32(v.w);
    dst[j] = o;
}

// ---------------------------------------------------------------------------
// tf32 mma.sync NT GEMM. 128x128 CTA, BK=32, 8 warps (4Mx2N, warp tile 32x64).
// 3-stage cp.async pipeline + register double-buffered fragments.
// ---------------------------------------------------------------------------
#define STAGES 3
#define BK 32
#define AST 36
#define STAGE_FLOATS (128 * AST * 2)
#define GEMM_SMEM (STAGES * STAGE_FLOATS * 4)   // 110592 bytes

__global__ __launch_bounds__(256, 2)
void gemm_mma_kernel(const float* __restrict__ A, const float* __restrict__ B,
                     float* __restrict__ C, int M, int N, int K)
{
    extern __shared__ float smf[];
    uint32_t sb = smem_u32(smf);
    const int tid = threadIdx.x;
    const int wid = tid >> 5;
    const int l   = tid & 31;
    const int g   = l >> 2;
    const int tg  = l & 3;
    const int wm  = wid >> 1;
    const int wn  = wid & 1;
    const int m0  = blockIdx.y * 128;
    const int n0  = blockIdx.x * 128;
    const int nchunk = K / BK;

    const int abase0 = (wm * 32 + g) * AST + tg;        // + s4*8
    const int bbase0 = (wn * 64 + g) * AST + tg;        // + nt*8*AST + s4*8

    auto issue = [&](int c, int s) {
        uint32_t sA = sb + (uint32_t)s * STAGE_FLOATS * 4;
        uint32_t sB = sA + 128u * AST * 4;
        const float* Ab = A + (size_t)m0 * K + c * BK;
        const float* Bb = B + (size_t)n0 * K + c * BK;
        #pragma unroll
        for (int i = 0; i < 4; i++) {
            int idx = tid + 256 * i;
            int row = idx >> 3;
            int c4  = idx & 7;
            uint32_t so = (uint32_t)(row * AST + c4 * 4) * 4;
            CP_ASYNC16(sA + so, Ab + (size_t)row * K + c4 * 4);
            CP_ASYNC16(sB + so, Bb + (size_t)row * K + c4 * 4);
        }
        CP_COMMIT();
    };

    float acc[2][8][4];
    #pragma unroll
    for (int mt = 0; mt < 2; mt++)
        #pragma unroll
        for (int nt = 0; nt < 8; nt++)
            #pragma unroll
            for (int q = 0; q < 4; q++) acc[mt][nt][q] = 0.f;

    #pragma unroll
    for (int s = 0; s < STAGES - 1; s++) issue(s, s);

    uint32_t af[2][2][4];   // [buf][mt][frag]
    uint32_t bf[2][8][2];   // [buf][nt][frag]

    for (int c = 0; c < nchunk; c++) {
        if (c < nchunk - 1) { CP_WAIT1(); } else { CP_WAIT0(); }
        __syncthreads();

        const uint32_t* Au = (const uint32_t*)(smf + (size_t)(c % STAGES) * STAGE_FLOATS);
        const uint32_t* Bu = Au + 128 * AST;

        // Prefetch k-step 0 fragments
        #pragma unroll
        for (int mt = 0; mt < 2; mt++) {
            int base = abase0 + mt * 16 * AST;
            af[0][mt][0] = Au[base];
            af[0][mt][1] = Au[base + 8 * AST];
            af[0][mt][2] = Au[base + 4];
            af[0][mt][3] = Au[base + 8 * AST + 4];
        }
        #pragma unroll
        for (int nt = 0; nt < 8; nt++) {
            int base = bbase0 + nt * 8 * AST;
            bf[0][nt][0] = Bu[base];
            bf[0][nt][1] = Bu[base + 4];
        }

        // Kick off next chunk's cp.async while frag LDS are in flight
        int cn = c + STAGES - 1;
        if (cn < nchunk) issue(cn, cn % STAGES);

        #pragma unroll
        for (int s4 = 0; s4 < 4; s4++) {
            const int cur = s4 & 1, nxt = cur ^ 1;
            if (s4 < 3) {   // prefetch next k-step fragments
                #pragma unroll
                for (int mt = 0; mt < 2; mt++) {
                    int base = abase0 + mt * 16 * AST + (s4 + 1) * 8;
                    af[nxt][mt][0] = Au[base];
                    af[nxt][mt][1] = Au[base + 8 * AST];
                    af[nxt][mt][2] = Au[base + 4];
                    af[nxt][mt][3] = Au[base + 8 * AST + 4];
                }
                #pragma unroll
                for (int nt = 0; nt < 8; nt++) {
                    int base = bbase0 + nt * 8 * AST + (s4 + 1) * 8;
                    bf[nxt][nt][0] = Bu[base];
                    bf[nxt][nt][1] = Bu[base + 4];
                }
            }
            #pragma unroll
            for (int mt = 0; mt < 2; mt++)
                #pragma unroll
                for (int nt = 0; nt < 8; nt++)
                    mma_tf32(acc[mt][nt][0], acc[mt][nt][1],
                             acc[mt][nt][2], acc[mt][nt][3],
                             af[cur][mt][0], af[cur][mt][1],
                             af[cur][mt][2], af[cur][mt][3],
                             bf[cur][nt][0], bf[cur][nt][1]);
        }
    }

    #pragma unroll
    for (int mt = 0; mt < 2; mt++) {
        int r = m0 + wm * 32 + mt * 16 + g;
        #pragma unroll
        for (int nt = 0; nt < 8; nt++) {
            int cc = n0 + wn * 64 + nt * 8 + tg * 2;
            *(float2*)&C[(size_t)r * N + cc] =
                make_float2(acc[mt][nt][0], acc[mt][nt][1]);
            *(float2*)&C[(size_t)(r + 8) * N + cc] =
                make_float2(acc[mt][nt][2], acc[mt][nt][3]);
        }
    }
}

// ---------------------------------------------------------------------------
// Tensor-core flash attention (tf32 mma.sync). Core unchanged from R5;
// occupancy raised to 4 CTAs/SM.
// ---------------------------------------------------------------------------
#define KST 68
#define VST 72
#define PST 68
#define ATT_SMEM ((64 * KST + 64 * VST + 64 * PST) * 4)   // 53248 bytes

__global__ __launch_bounds__(128, 4) void attn_mma_kernel(
    const float* __restrict__ qkv, float* __restrict__ out)
{
    extern __shared__ float sm[];
    float* Ks = sm;
    float* Vs = sm + 64 * KST;
    float* Ps = sm + 64 * KST + 64 * VST;
    uint32_t* Ku = (uint32_t*)Ks;
    uint32_t* Vu = (uint32_t*)Vs;
    uint32_t* Pu = (uint32_t*)Ps;

    const int tid = threadIdx.x;
    const int w  = tid >> 5;
    const int l  = tid & 31;
    const int g  = l >> 2;
    const int tg = l & 3;
    const int qt = blockIdx.x;
    const int h  = blockIdx.y;
    const int b  = blockIdx.z;
    const int q0 = qt * 64;
    const size_t bh = (size_t)b * Sz * D3z + (size_t)h * HDz;
    const float NEG_INF = -__int_as_float(0x7f800000);

    // Stage Q (scaled by 1/8, tf32-rounded) into Ps
    for (int idx = tid; idx < 1024; idx += 128) {
        int r = idx >> 4, c4 = (idx & 15) << 2;
        float4 v = *(const float4*)(qkv + bh + (size_t)(q0 + r) * D3z + c4);
        uint4 o4;
        o4.x = f2tf32(v.x * 0.125f); o4.y = f2tf32(v.y * 0.125f);
        o4.z = f2tf32(v.z * 0.125f); o4.w = f2tf32(v.w * 0.125f);
        *(uint4*)&Pu[r * PST + c4] = o4;
    }
    __syncthreads();

    uint32_t qa[8][4];
    const int pr0 = (w * 16 + g) * PST;
    const int pr1 = (w * 16 + g + 8) * PST;
    #pragma unroll
    for (int kk = 0; kk < 8; kk++) {
        qa[kk][0] = Pu[pr0 + kk * 8 + tg];
        qa[kk][1] = Pu[pr1 + kk * 8 + tg];
        qa[kk][2] = Pu[pr0 + kk * 8 + tg + 4];
        qa[kk][3] = Pu[pr1 + kk * 8 + tg + 4];
    }

    float o[8][4];
    #pragma unroll
    for (int nt = 0; nt < 8; nt++)
        #pragma unroll
        for (int q = 0; q < 4; q++) o[nt][q] = 0.f;
    float m0 = NEG_INF, m1 = NEG_INF, l0 = 0.f, l1 = 0.f;

    for (int kt = 0; kt <= qt; kt++) {
        __syncthreads();
        for (int idx = tid; idx < 1024; idx += 128) {
            int r = idx >> 4, c4 = (idx & 15) << 2;
            const float* p = qkv + bh + (size_t)(kt * 64 + r) * D3z + Dz + c4;
            float4 kv = *(const float4*)p;
            float4 vv = *(const float4*)(p + Dz);
            uint4 k4, v4;
            k4.x = f2tf32(kv.x); k4.y = f2tf32(kv.y);
            k4.z = f2tf32(kv.z); k4.w = f2tf32(kv.w);
            v4.x = f2tf32(vv.x); v4.y = f2tf32(vv.y);
            v4.z = f2tf32(vv.z); v4.w = f2tf32(vv.w);
            *(uint4*)&Ku[r * KST + c4] = k4;
            *(uint4*)&Vu[r * VST + c4] = v4;
        }
        __syncthreads();

        float s[8][4];
        #pragma unroll
        for (int nt = 0; nt < 8; nt++)
            #pragma unroll
            for (int q = 0; q < 4; q++) s[nt][q] = 0.f;

        #pragma unroll
        for (int kk = 0; kk < 8; kk++) {
            #pragma unroll
            for (int nt = 0; nt < 8; nt++) {
                int kb = (nt * 8 + g) * KST + kk * 8 + tg;
                uint32_t b0 = Ku[kb];
                uint32_t b1 = Ku[kb + 4];
                mma_tf32(s[nt][0], s[nt][1], s[nt][2], s[nt][3],
                         qa[kk][0], qa[kk][1], qa[kk][2], qa[kk][3], b0, b1);
            }
        }

        if (kt == qt) {
            int i0 = w * 16 + g, i1 = i0 + 8;
            #pragma unroll
            for (int nt = 0; nt < 8; nt++) {
                int j0 = nt * 8 + 2 * tg;
                if (j0     > i0) s[nt][0] = NEG_INF;
                if (j0 + 1 > i0) s[nt][1] = NEG_INF;
                if (j0     > i1) s[nt][2] = NEG_INF;
                if (j0 + 1 > i1) s[nt][3] = NEG_INF;
            }
        }

        float r0 = NEG_INF, r1 = NEG_INF;
        #pragma unroll
        for (int nt = 0; nt < 8; nt++) {
            r0 = fmaxf(r0, fmaxf(s[nt][0], s[nt][1]));
            r1 = fmaxf(r1, fmaxf(s[nt][2], s[nt][3]));
        }
        r0 = fmaxf(r0, __shfl_xor_sync(0xffffffffu, r0, 1));
        r0 = fmaxf(r0, __shfl_xor_sync(0xffffffffu, r0, 2));
        r1 = fmaxf(r1, __shfl_xor_sync(0xffffffffu, r1, 1));
        r1 = fmaxf(r1, __shfl_xor_sync(0xffffffffu, r1, 2));

        float nm0 = fmaxf(m0, r0), nm1 = fmaxf(m1, r1);
        float a0 = __expf(m0 - nm0), a1 = __expf(m1 - nm1);
        float sum0 = 0.f, sum1 = 0.f;
        #pragma unroll
        for (int nt = 0; nt < 8; nt++) {
            s[nt][0] = __expf(s[nt][0] - nm0);
            s[nt][1] = __expf(s[nt][1] - nm0);
            s[nt][2] = __expf(s[nt][2] - nm1);
            s[nt][3] = __expf(s[nt][3] - nm1);
            sum0 += s[nt][0] + s[nt][1];
            sum1 += s[nt][2] + s[nt][3];
        }
        sum0 += __shfl_xor_sync(0xffffffffu, sum0, 1);
        sum0 += __shfl_xor_sync(0xffffffffu, sum0, 2);
        sum1 += __shfl_xor_sync(0xffffffffu, sum1, 1);
        sum1 += __shfl_xor_sync(0xffffffffu, sum1, 2);
        m0 = nm0; m1 = nm1;
        l0 = l0 * a0 + sum0;
        l1 = l1 * a1 + sum1;

        #pragma unroll
        for (int nt = 0; nt < 8; nt++) {
            o[nt][0] *= a0; o[nt][1] *= a0;
            o[nt][2] *= a1; o[nt][3] *= a1;
        }

        #pragma unroll
        for (int nt = 0; nt < 8; nt++) {
            int c0 = nt * 8 + 2 * tg;
            Pu[pr0 + c0]     = f2tf32(s[nt][0]);
            Pu[pr0 + c0 + 1] = f2tf32(s[nt][1]);
            Pu[pr1 + c0]     = f2tf32(s[nt][2]);
            Pu[pr1 + c0 + 1] = f2tf32(s[nt][3]);
        }
        __syncwarp();

        #pragma unroll
        for (int kk = 0; kk < 8; kk++) {
            uint32_t pa0 = Pu[pr0 + kk * 8 + tg];
            uint32_t pa1 = Pu[pr1 + kk * 8 + tg];
            uint32_t pa2 = Pu[pr0 + kk * 8 + tg + 4];
            uint32_t pa3 = Pu[pr1 + kk * 8 + tg + 4];
            #pragma unroll
            for (int nt = 0; nt < 8; nt++) {
                uint32_t b0 = Vu[(kk * 8 + tg) * VST + nt * 8 + g];
                uint32_t b1 = Vu[(kk * 8 + tg + 4) * VST + nt * 8 + g];
                mma_tf32(o[nt][0], o[nt][1], o[nt][2], o[nt][3],
                         pa0, pa1, pa2, pa3, b0, b1);
            }
        }
    }

    float i0v = 1.f / l0, i1v = 1.f / l1;
    uint32_t* o0p = (uint32_t*)(out + (size_t)(b * Sz + q0 + w * 16 + g) * Dz + h * HDz);
    uint32_t* o1p = o0p + (size_t)8 * Dz;
    #pragma unroll
    for (int nt = 0; nt < 8; nt++) {
        int cc = nt * 8 + 2 * tg;
        uint2 v0 = make_uint2(f2tf32(o[nt][0] * i0v), f2tf32(o[nt][1] * i0v));
        uint2 v1 = make_uint2(f2tf32(o[nt][2] * i1v), f2tf32(o[nt][3] * i1v));
        *(uint2*)(o0p + cc) = v0;
        *(uint2*)(o1p + cc) = v1;
    }
}

// ---------------------------------------------------------------------------
extern "C" void kernel_launch(void* const* d_in, const int* in_sizes, int n_in,
                              void* d_out, int out_size)
{
    const float* x      = (const float*)d_in[0];
    const float* w_qkv  = (const float*)d_in[1];
    const float* w_proj = (const float*)d_in[2];
    float* out = (float*)d_out;

    void *qkvp, *attnp, *xp, *wqp, *wpp;
    cudaGetSymbolAddress(&qkvp, g_qkv);
    cudaGetSymbolAddress(&attnp, g_attn);
    cudaGetSymbolAddress(&xp, g_x);
    cudaGetSymbolAddress(&wqp, g_wq);
    cudaGetSymbolAddress(&wpp, g_wp);

    cudaFuncSetAttribute(attn_mma_kernel,
                         cudaFuncAttributeMaxDynamicSharedMemorySize, ATT_SMEM);
    cudaFuncSetAttribute(gemm_mma_kernel,
                         cudaFuncAttributeMaxDynamicSharedMemorySize, GEMM_SMEM);

    const int M = Mz;

    // 0) tf32-round all GEMM inputs in one pass
    {
        int total = N4_X + N4_WQ + N4_WP;
        cvt_all_kernel<<<(total + 255) / 256, 256>>>(
            x, (float*)xp, w_qkv, (float*)wqp, w_proj, (float*)wpp);
    }

    // 1) QKV projection (tensor cores): [8192,1024] x [3072,1024]^T
    gemm_mma_kernel<<<dim3(D3z / 128, M / 128), 256, GEMM_SMEM>>>(
        (const float*)xp, (const float*)wqp, (float*)qkvp, M, D3z, Dz);

    // 2) Causal flash attention (tensor cores) -> g_attn (tf32-rounded)
    attn_mma_kernel<<<dim3(Sz / 64, Hz, Bz), 128, ATT_SMEM>>>(
        (const float*)qkvp, (float*)attnp);

    // 3) Output projection (tensor cores): [8192,1024] x [1024,1024]^T
    gemm_mma_kernel<<<dim3(Dz / 128, M / 128), 256, GEMM_SMEM>>>(
        (const float*)attnp, (const float*)wpp, out, M, Dz, Dz);
}